// round 1
// baseline (speedup 1.0000x reference)
#include <cuda_runtime.h>

// DirectionalStateScan2D: B=8, C=256, H=128, W=128, fp32.
// out = m0*LR + m1*RL + m2*TB + m3*BT, each a first-order IIR
// s_t = d*s_{t-1} + (1-d)*scale*x_t with per-channel params.
//
// One CTA per (b,c) plane. Plane lives in padded SMEM (stride 129 floats)
// so row-serial AND column-serial accesses are bank-conflict-free.
// Threads 0-127 do forward scans, threads 128-255 do backward scans into a
// second accumulator; writeout sums both.

#define Hh 128
#define Ww 128
#define Cc 256
#define STRIDE 129            // 128 + 1 pad: conflict-free for both axes
#define PLANE (Hh * Ww)
#define NTHREADS 256
#define SMEM_FLOATS (3 * Hh * STRIDE)

__global__ __launch_bounds__(NTHREADS, 1)
void dss2d_kernel(const float* __restrict__ x,
                  const float* __restrict__ decay_logits,
                  const float* __restrict__ mix_logits,
                  const float* __restrict__ input_scale,
                  float* __restrict__ out)
{
    extern __shared__ float smem[];
    float* xs   = smem;                     // [H][STRIDE]
    float* accA = smem + Hh * STRIDE;       // forward dirs (LR, TB)
    float* accB = smem + 2 * Hh * STRIDE;   // backward dirs (RL, BT)

    const int p    = blockIdx.x;            // plane index b*C + c
    const int ch   = p % Cc;
    const int tid  = threadIdx.x;
    const int lane = tid & 31;
    const int rot  = (lane >> 3) & 3;       // STS bank-rotation
    const bool fwd = (tid < 128);

    // ---- per-channel parameters (cheap, broadcast loads hit L1/L2) ----
    const float ml0 = mix_logits[0 * Cc + ch];
    const float ml1 = mix_logits[1 * Cc + ch];
    const float ml2 = mix_logits[2 * Cc + ch];
    const float ml3 = mix_logits[3 * Cc + ch];
    const float mmax = fmaxf(fmaxf(ml0, ml1), fmaxf(ml2, ml3));
    const float e0 = expf(ml0 - mmax);
    const float e1 = expf(ml1 - mmax);
    const float e2 = expf(ml2 - mmax);
    const float e3 = expf(ml3 - mmax);
    const float inv = 1.0f / (e0 + e1 + e2 + e3);

    const int dirA = fwd ? 0 : 1;   // horizontal dir for this thread
    const int dirB = fwd ? 2 : 3;   // vertical dir for this thread

    float dA = 1.0f / (1.0f + expf(-decay_logits[dirA * Cc + ch]));
    dA = fminf(fmaxf(dA, 0.05f), 0.995f);
    float dB = 1.0f / (1.0f + expf(-decay_logits[dirB * Cc + ch]));
    dB = fminf(fmaxf(dB, 0.05f), 0.995f);

    const float scA = 1.0f + tanhf(input_scale[dirA * Cc + ch]);
    const float scB = 1.0f + tanhf(input_scale[dirB * Cc + ch]);
    const float cA = (1.0f - dA) * scA;   // input coefficient
    const float cB = (1.0f - dB) * scB;
    const float mA = (fwd ? e0 : e1) * inv;  // mix weight
    const float mB = (fwd ? e2 : e3) * inv;

    // ---- load plane into padded SMEM (float4 LDG, rotated scalar STS) ----
    const float4* __restrict__ src =
        reinterpret_cast<const float4*>(x + (size_t)p * PLANE);
    #pragma unroll
    for (int k = 0; k < 16; k++) {
        const int fidx = tid + k * NTHREADS;       // 0..4095 float4s
        const float4 v = src[fidx];
        const int h  = fidx >> 5;                  // 32 float4 per row
        const int w4 = (fidx & 31) << 2;
        float a[4] = {v.x, v.y, v.z, v.w};
        float* dst = xs + h * STRIDE + w4;
        #pragma unroll
        for (int j = 0; j < 4; j++) {
            const int jj = (j + rot) & 3;          // rotate to avoid 4-way conflict
            dst[jj] = a[jj];
        }
    }
    __syncthreads();

    // ---- Phase A: horizontal scans (one thread per row) ----
    {
        const int r = tid & 127;
        const float* __restrict__ xrow = xs + r * STRIDE;
        float* __restrict__ arow = (fwd ? accA : accB) + r * STRIDE;
        float s = 0.0f;
        if (fwd) {
            #pragma unroll 8
            for (int w = 0; w < Ww; w++) {
                s = fmaf(dA, s, cA * xrow[w]);
                arow[w] = mA * s;
            }
        } else {
            #pragma unroll 8
            for (int w = Ww - 1; w >= 0; w--) {
                s = fmaf(dA, s, cA * xrow[w]);
                arow[w] = mA * s;
            }
        }
    }
    __syncthreads();

    // ---- Phase B: vertical scans (one thread per column) ----
    {
        const int c = tid & 127;
        const float* __restrict__ xcol = xs + c;
        float* __restrict__ acol = (fwd ? accA : accB) + c;
        float s = 0.0f;
        if (fwd) {
            #pragma unroll 8
            for (int h = 0; h < Hh; h++) {
                const int idx = h * STRIDE;
                s = fmaf(dB, s, cB * xcol[idx]);
                acol[idx] += mB * s;
            }
        } else {
            #pragma unroll 8
            for (int h = Hh - 1; h >= 0; h--) {
                const int idx = h * STRIDE;
                s = fmaf(dB, s, cB * xcol[idx]);
                acol[idx] += mB * s;
            }
        }
    }
    __syncthreads();

    // ---- writeout: out = accA + accB (float4 STG, rotated LDS) ----
    float4* __restrict__ dst =
        reinterpret_cast<float4*>(out + (size_t)p * PLANE);
    #pragma unroll
    for (int k = 0; k < 16; k++) {
        const int fidx = tid + k * NTHREADS;
        const int h  = fidx >> 5;
        const int w4 = (fidx & 31) << 2;
        const float* a = accA + h * STRIDE + w4;
        const float* b = accB + h * STRIDE + w4;
        float v[4];
        #pragma unroll
        for (int j = 0; j < 4; j++) {
            const int jj = (j + rot) & 3;
            v[jj] = a[jj] + b[jj];
        }
        dst[fidx] = make_float4(v[0], v[1], v[2], v[3]);
    }
}

extern "C" void kernel_launch(void* const* d_in, const int* in_sizes, int n_in,
                              void* d_out, int out_size)
{
    const float* x            = (const float*)d_in[0];
    const float* decay_logits = (const float*)d_in[1];
    const float* mix_logits   = (const float*)d_in[2];
    const float* input_scale  = (const float*)d_in[3];
    float* out = (float*)d_out;

    const int smem_bytes = SMEM_FLOATS * sizeof(float);  // 198144
    cudaFuncSetAttribute(dss2d_kernel,
                         cudaFuncAttributeMaxDynamicSharedMemorySize,
                         smem_bytes);

    const int nplanes = 8 * Cc;   // B * C = 2048
    dss2d_kernel<<<nplanes, NTHREADS, smem_bytes>>>(
        x, decay_logits, mix_logits, input_scale, out);
}

// round 2
// speedup vs baseline: 1.2670x; 1.2670x over previous
#include <cuda_runtime.h>

// DirectionalStateScan2D: B=8, C=256, H=128, W=128, fp32.
// out = m0*LR + m1*RL + m2*TB + m3*BT, first-order IIR per direction,
// s_t = d*s_{t-1} + (1-d)*scale*x_t, constant per-channel coefficients.
//
// One CTA per (b,c) plane. Constant decay => linear scan parallelizes:
// per-lane 4-elem local scan + 5-step Hillis-Steele carry scan (multipliers
// d^4..d^64) + fixup. XOR-swizzled SMEM gives conflict-free row float4 AND
// column gather access. Vertical pass -> acc; horizontal pass fused with
// final combine + coalesced float4 STG.

#define Hh 128
#define Ww 128
#define Cc 256
#define PLANE (Hh * Ww)
#define NT 512
#define NW (NT / 32)
#define FULL 0xFFFFFFFFu

struct DirP {
    float d1, d2, d3, d4;   // d^1..d^4
    float q1, q2, q3, q4;   // d^8, d^16, d^32, d^64
    float c;                // (1-d)*scale
};

__device__ __forceinline__ DirP make_dir(const float* __restrict__ decay_logits,
                                         const float* __restrict__ input_scale,
                                         int dir, int ch)
{
    float d = 1.0f / (1.0f + expf(-decay_logits[dir * Cc + ch]));
    d = fminf(fmaxf(d, 0.05f), 0.995f);
    float sc = 1.0f + tanhf(input_scale[dir * Cc + ch]);
    DirP P;
    P.d1 = d;
    P.d2 = d * d;
    P.d3 = P.d2 * d;
    P.d4 = P.d2 * P.d2;
    P.q1 = P.d4 * P.d4;
    P.q2 = P.q1 * P.q1;
    P.q3 = P.q2 * P.q2;
    P.q4 = P.q3 * P.q3;
    P.c  = (1.0f - d) * sc;
    return P;
}

// Forward scan: element order x0..x3 within lane, lanes ascending.
__device__ __forceinline__ void scan_fwd(const DirP& P, int lane,
        float x0, float x1, float x2, float x3,
        float& s0, float& s1, float& s2, float& s3)
{
    float l0 = P.c * x0;
    float l1 = fmaf(P.d1, l0, P.c * x1);
    float l2 = fmaf(P.d1, l1, P.c * x2);
    float l3 = fmaf(P.d1, l2, P.c * x3);
    float t = l3, u;
    u = __shfl_up_sync(FULL, t, 1);  if (lane >= 1)  t = fmaf(P.d4, u, t);
    u = __shfl_up_sync(FULL, t, 2);  if (lane >= 2)  t = fmaf(P.q1, u, t);
    u = __shfl_up_sync(FULL, t, 4);  if (lane >= 4)  t = fmaf(P.q2, u, t);
    u = __shfl_up_sync(FULL, t, 8);  if (lane >= 8)  t = fmaf(P.q3, u, t);
    u = __shfl_up_sync(FULL, t, 16); if (lane >= 16) t = fmaf(P.q4, u, t);
    float pre = __shfl_up_sync(FULL, t, 1);
    pre = (lane == 0) ? 0.0f : pre;
    s0 = fmaf(P.d1, pre, l0);
    s1 = fmaf(P.d2, pre, l1);
    s2 = fmaf(P.d3, pre, l2);
    s3 = fmaf(P.d4, pre, l3);
}

// Backward scan: element order x3..x0 within lane, lanes descending.
__device__ __forceinline__ void scan_bwd(const DirP& P, int lane,
        float x0, float x1, float x2, float x3,
        float& s0, float& s1, float& s2, float& s3)
{
    float r3 = P.c * x3;
    float r2 = fmaf(P.d1, r3, P.c * x2);
    float r1 = fmaf(P.d1, r2, P.c * x1);
    float r0 = fmaf(P.d1, r1, P.c * x0);
    float t = r0, u;
    u = __shfl_down_sync(FULL, t, 1);  if (lane <= 30) t = fmaf(P.d4, u, t);
    u = __shfl_down_sync(FULL, t, 2);  if (lane <= 29) t = fmaf(P.q1, u, t);
    u = __shfl_down_sync(FULL, t, 4);  if (lane <= 27) t = fmaf(P.q2, u, t);
    u = __shfl_down_sync(FULL, t, 8);  if (lane <= 23) t = fmaf(P.q3, u, t);
    u = __shfl_down_sync(FULL, t, 16); if (lane <= 15) t = fmaf(P.q4, u, t);
    float pre = __shfl_down_sync(FULL, t, 1);
    pre = (lane == 31) ? 0.0f : pre;
    s3 = fmaf(P.d1, pre, r3);
    s2 = fmaf(P.d2, pre, r2);
    s1 = fmaf(P.d3, pre, r1);
    s0 = fmaf(P.d4, pre, r0);
}

__global__ __launch_bounds__(NT, 1)
void dss2d_kernel(const float* __restrict__ x,
                  const float* __restrict__ decay_logits,
                  const float* __restrict__ mix_logits,
                  const float* __restrict__ input_scale,
                  float* __restrict__ out)
{
    extern __shared__ float smem[];
    float* xs  = smem;           // 128x128, XOR-swizzled
    float* acc = smem + PLANE;   // vertical results, same swizzle

    const int p    = blockIdx.x;
    const int ch   = p & (Cc - 1);
    const int tid  = threadIdx.x;
    const int lane = tid & 31;
    const int wid  = tid >> 5;

    // mix weights (softmax over 4 directions)
    float ml0 = mix_logits[ch];
    float ml1 = mix_logits[Cc + ch];
    float ml2 = mix_logits[2 * Cc + ch];
    float ml3 = mix_logits[3 * Cc + ch];
    float mx = fmaxf(fmaxf(ml0, ml1), fmaxf(ml2, ml3));
    float e0 = expf(ml0 - mx), e1 = expf(ml1 - mx);
    float e2 = expf(ml2 - mx), e3 = expf(ml3 - mx);
    float minv = 1.0f / (e0 + e1 + e2 + e3);
    const float m0 = e0 * minv, m1 = e1 * minv;
    const float m2 = e2 * minv, m3 = e3 * minv;

    // ---- load plane into swizzled SMEM (float4 LDG + float4 STS) ----
    const float4* __restrict__ src =
        reinterpret_cast<const float4*>(x + (size_t)p * PLANE);
    #pragma unroll
    for (int k = 0; k < PLANE / 4 / NT; k++) {   // 8 iterations
        const int fidx = tid + k * NT;           // 0..4095
        const float4 v = src[fidx];
        const int h = fidx >> 5;                 // 32 float4 per row
        const int g = fidx & 31;
        const int pg = g ^ ((h >> 2) & 31);
        *reinterpret_cast<float4*>(xs + h * 128 + (pg << 2)) = v;
    }
    __syncthreads();

    // ---- vertical: TB (dir 2) + BT (dir 3), warp per column -> acc ----
    {
        const DirP PT = make_dir(decay_logits, input_scale, 2, ch);
        const DirP PB = make_dir(decay_logits, input_scale, 3, ch);
        #pragma unroll
        for (int it = 0; it < 128 / NW; it++) {
            const int c = wid + it * NW;
            // rows 4*lane..4*lane+3; group swizzle constant across j
            const int off = (((c >> 2) ^ lane) << 2) + (c & 3);
            const int i0 = (4 * lane) * 128 + off;
            const float x0 = xs[i0];
            const float x1 = xs[i0 + 128];
            const float x2 = xs[i0 + 256];
            const float x3 = xs[i0 + 384];
            float t0, t1, t2, t3, b0, b1, b2, b3;
            scan_fwd(PT, lane, x0, x1, x2, x3, t0, t1, t2, t3);
            scan_bwd(PB, lane, x0, x1, x2, x3, b0, b1, b2, b3);
            acc[i0]       = fmaf(m2, t0, m3 * b0);
            acc[i0 + 128] = fmaf(m2, t1, m3 * b1);
            acc[i0 + 256] = fmaf(m2, t2, m3 * b2);
            acc[i0 + 384] = fmaf(m2, t3, m3 * b3);
        }
    }
    __syncthreads();

    // ---- horizontal: LR (dir 0) + RL (dir 1), warp per row, fused STG ----
    {
        const DirP PL = make_dir(decay_logits, input_scale, 0, ch);
        const DirP PR = make_dir(decay_logits, input_scale, 1, ch);
        float4* __restrict__ dst =
            reinterpret_cast<float4*>(out + (size_t)p * PLANE);
        #pragma unroll
        for (int it = 0; it < 128 / NW; it++) {
            const int h = wid + it * NW;
            const int pg = lane ^ ((h >> 2) & 31);
            const int idx = h * 128 + (pg << 2);
            const float4 v = *reinterpret_cast<const float4*>(xs + idx);
            const float4 a = *reinterpret_cast<const float4*>(acc + idx);
            float l0, l1, l2, l3, r0, r1, r2, r3;
            scan_fwd(PL, lane, v.x, v.y, v.z, v.w, l0, l1, l2, l3);
            scan_bwd(PR, lane, v.x, v.y, v.z, v.w, r0, r1, r2, r3);
            float4 o;
            o.x = fmaf(m0, l0, fmaf(m1, r0, a.x));
            o.y = fmaf(m0, l1, fmaf(m1, r1, a.y));
            o.z = fmaf(m0, l2, fmaf(m1, r2, a.z));
            o.w = fmaf(m0, l3, fmaf(m1, r3, a.w));
            dst[h * 32 + lane] = o;
        }
    }
}

extern "C" void kernel_launch(void* const* d_in, const int* in_sizes, int n_in,
                              void* d_out, int out_size)
{
    const float* x            = (const float*)d_in[0];
    const float* decay_logits = (const float*)d_in[1];
    const float* mix_logits   = (const float*)d_in[2];
    const float* input_scale  = (const float*)d_in[3];
    float* out = (float*)d_out;

    const int smem_bytes = 2 * PLANE * sizeof(float);  // 131072
    cudaFuncSetAttribute(dss2d_kernel,
                         cudaFuncAttributeMaxDynamicSharedMemorySize,
                         smem_bytes);

    const int nplanes = 8 * Cc;   // 2048
    dss2d_kernel<<<nplanes, NT, smem_bytes>>>(
        x, decay_logits, mix_logits, input_scale, out);
}